// round 10
// baseline (speedup 1.0000x reference)
#include <cuda_runtime.h>
#include <cuda_fp16.h>
#include <cstdint>

// Problem constants
#define BB   4
#define LL   2048
#define AD   1024
#define NH   16
#define HD   64
#define MM   (BB*LL)   // 8192

// ---------------------------------------------------------------------------
// Scratch (device globals)
// ---------------------------------------------------------------------------
__device__ __half g_acts [3 * MM * AD];    // fp16 activations q|k|v
__device__ __half g_wt   [4 * AD * AD];    // weights^T fp16 (q,k,v,o)
__device__ __half g_heads[3 * MM * AD];    // head planes Q(prescaled)|K|V
__device__ __half g_ao   [MM * AD];        // attention output fp16 [M,1024]

// ---------------------------------------------------------------------------
// Helpers (plain sm_103-legal: cp.async, ldmatrix, mma.sync)
// ---------------------------------------------------------------------------
__device__ __forceinline__ uint32_t smem_u32(const void* p) {
    uint32_t a;
    asm("{ .reg .u64 t; cvta.to.shared.u64 t, %1; cvt.u32.u64 %0, t; }" : "=r"(a) : "l"(p));
    return a;
}
#define CP_COMMIT()  asm volatile("cp.async.commit_group;" ::: "memory")
#define CP_WAIT(n)   asm volatile("cp.async.wait_group %0;" :: "n"(n) : "memory")

__device__ __forceinline__ uint32_t pack_h2(__half a, __half b) {
    return (uint32_t)__half_as_ushort(a) | ((uint32_t)__half_as_ushort(b) << 16);
}
__device__ __forceinline__ void ldm_x4(uint32_t& r0, uint32_t& r1, uint32_t& r2, uint32_t& r3,
                                       uint32_t addr) {
    asm volatile("ldmatrix.sync.aligned.m8n8.x4.shared.b16 {%0,%1,%2,%3}, [%4];"
                 : "=r"(r0), "=r"(r1), "=r"(r2), "=r"(r3) : "r"(addr));
}
__device__ __forceinline__ void ldm_x4_t(uint32_t& r0, uint32_t& r1, uint32_t& r2, uint32_t& r3,
                                         uint32_t addr) {
    asm volatile("ldmatrix.sync.aligned.m8n8.x4.trans.shared.b16 {%0,%1,%2,%3}, [%4];"
                 : "=r"(r0), "=r"(r1), "=r"(r2), "=r"(r3) : "r"(addr));
}
__device__ __forceinline__ void mma16816(float* d, const uint32_t* a, uint32_t b0, uint32_t b1) {
    asm volatile(
        "mma.sync.aligned.m16n8k16.row.col.f32.f16.f16.f32 "
        "{%0,%1,%2,%3}, {%4,%5,%6,%7}, {%8,%9}, {%0,%1,%2,%3};"
        : "+f"(d[0]), "+f"(d[1]), "+f"(d[2]), "+f"(d[3])
        : "r"(a[0]), "r"(a[1]), "r"(a[2]), "r"(a[3]), "r"(b0), "r"(b1));
}

// ---------------------------------------------------------------------------
// conv_act fused: 3 inputs fp32 [M,1024] -> fp16, selected by blockIdx.y
// ---------------------------------------------------------------------------
__global__ void conv_act3(const float* __restrict__ X0, const float* __restrict__ X1,
                          const float* __restrict__ X2, __half* __restrict__ Y)
{
    const int z = blockIdx.y;
    const float* X = (z == 0) ? X0 : (z == 1) ? X1 : X2;
    int m = blockIdx.x;
    int c = threadIdx.x * 4;
    float4 v = *reinterpret_cast<const float4*>(X + (size_t)m * AD + c);
    uint2 o;
    o.x = pack_h2(__float2half_rn(v.x), __float2half_rn(v.y));
    o.y = pack_h2(__float2half_rn(v.z), __float2half_rn(v.w));
    *reinterpret_cast<uint2*>(Y + (size_t)z * MM * AD + (size_t)m * AD + c) = o;
}

// ---------------------------------------------------------------------------
// conv_wt fused: 4 weights W[K][N] fp32 -> Wt[N][K] fp16, selected by blockIdx.z
// ---------------------------------------------------------------------------
__global__ void conv_wt4(const float* __restrict__ W0, const float* __restrict__ W1,
                         const float* __restrict__ W2, const float* __restrict__ W3,
                         __half* __restrict__ WtBase)
{
    __shared__ float s[32][33];
    const int z = blockIdx.z;
    const float* W = (z == 0) ? W0 : (z == 1) ? W1 : (z == 2) ? W2 : W3;
    __half* Wt = WtBase + (size_t)z * AD * AD;
    int n0 = blockIdx.x * 32;
    int k0 = blockIdx.y * 32;
    int tx = threadIdx.x, ty = threadIdx.y;   // (32, 8)
#pragma unroll
    for (int i = 0; i < 4; ++i)
        s[ty + 8 * i][tx] = W[(size_t)(k0 + ty + 8 * i) * AD + n0 + tx];
    __syncthreads();
#pragma unroll
    for (int i = 0; i < 4; ++i) {
        int n = n0 + ty + 8 * i;
        int k = k0 + tx;
        Wt[(size_t)n * AD + k] = __float2half_rn(s[tx][ty + 8 * i]);
    }
}

// ---------------------------------------------------------------------------
// fp16 mma GEMM core (unchanged, proven).
// CTA 128x128, K chunks 64, cp.async double buffer, swizzled 128B smem rows.
// ---------------------------------------------------------------------------
#define GK_NC 16
#define SA0   0
#define SA1   16384
#define SB0   32768
#define SB1   49152
#define G_SMEM 65536

__device__ __forceinline__ void load_tile_cp(uint32_t sbase, uint32_t soff,
                                             const __half* __restrict__ g,
                                             int row0, int kc, int tid)
{
#pragma unroll
    for (int i = 0; i < 4; ++i) {
        int idx = i * 256 + tid;
        int r = idx >> 3, seg = idx & 7;
        const char* src = (const char*)g + ((size_t)(row0 + r) * AD + kc) * 2 + seg * 16;
        uint32_t dst = sbase + soff + r * 128 + ((seg * 16) ^ ((r & 7) * 16));
        asm volatile("cp.async.cg.shared.global [%0], [%1], 16;" :: "r"(dst), "l"(src));
    }
}

__device__ __forceinline__ void gemm_body(const __half* __restrict__ A,
                                          const __half* __restrict__ Bt,
                                          const float* __restrict__ bias,
                                          float* __restrict__ C,
                                          __half* __restrict__ outH,
                                          float oscale,
                                          char* smem)
{
    const uint32_t sbase = smem_u32(smem);
    const int tid  = threadIdx.x;
    const int warp = tid >> 5;
    const int lane = tid & 31;
    const int bn = blockIdx.x * 128;
    const int bm = blockIdx.y * 128;

    const int wm0 = (warp >> 2) * 64;
    const int wn0 = (warp & 3) * 32;

    float d[4][4][4];
#pragma unroll
    for (int im = 0; im < 4; ++im)
#pragma unroll
        for (int jt = 0; jt < 4; ++jt)
#pragma unroll
            for (int q = 0; q < 4; ++q) d[im][jt][q] = 0.f;

    uint32_t a_rb[4], a_sw[4];
#pragma unroll
    for (int im = 0; im < 4; ++im) {
        int row = wm0 + im * 16 + (lane & 15);
        a_rb[im] = row * 128;
        a_sw[im] = (row & 7) * 16;
    }
    const uint32_t a_kb = (lane >> 4) * 16;
    uint32_t b_rb[2], b_sw[2];
#pragma unroll
    for (int jn = 0; jn < 2; ++jn) {
        int row = wn0 + jn * 16 + (lane & 7) + ((lane >> 4) << 3);
        b_rb[jn] = row * 128;
        b_sw[jn] = (row & 7) * 16;
    }
    const uint32_t b_kb = ((lane >> 3) & 1) * 16;

    load_tile_cp(sbase, SA0, A,  bm, 0, tid);
    load_tile_cp(sbase, SB0, Bt, bn, 0, tid);
    CP_COMMIT();

    for (int i = 0; i < GK_NC; ++i) {
        const uint32_t aoff = (i & 1) ? SA1 : SA0;
        const uint32_t boff = (i & 1) ? SB1 : SB0;
        if (i + 1 < GK_NC) {
            load_tile_cp(sbase, (i & 1) ? SA0 : SA1, A,  bm, (i + 1) * 64, tid);
            load_tile_cp(sbase, (i & 1) ? SB0 : SB1, Bt, bn, (i + 1) * 64, tid);
            CP_COMMIT();
            CP_WAIT(1);
        } else {
            CP_WAIT(0);
        }
        __syncthreads();

#pragma unroll
        for (int ks = 0; ks < 4; ++ks) {
            const uint32_t kb = ks * 32;
            uint32_t af[4][4];
#pragma unroll
            for (int im = 0; im < 4; ++im)
                ldm_x4(af[im][0], af[im][1], af[im][2], af[im][3],
                       sbase + aoff + a_rb[im] + ((kb + a_kb) ^ a_sw[im]));
            uint32_t bf[4][2];
#pragma unroll
            for (int jn = 0; jn < 2; ++jn) {
                uint32_t r0, r1, r2, r3;
                ldm_x4(r0, r1, r2, r3,
                       sbase + boff + b_rb[jn] + ((kb + b_kb) ^ b_sw[jn]));
                bf[jn * 2][0] = r0; bf[jn * 2][1] = r1;
                bf[jn * 2 + 1][0] = r2; bf[jn * 2 + 1][1] = r3;
            }
#pragma unroll
            for (int im = 0; im < 4; ++im)
#pragma unroll
                for (int jt = 0; jt < 4; ++jt)
                    mma16816(d[im][jt], af[im], bf[jt][0], bf[jt][1]);
        }
        __syncthreads();
    }

    if (outH == nullptr) {
#pragma unroll
        for (int jt = 0; jt < 4; ++jt) {
            const int c0 = bn + wn0 + jt * 8 + 2 * (lane & 3);
            float2 bb = *reinterpret_cast<const float2*>(bias + c0);
#pragma unroll
            for (int im = 0; im < 4; ++im) {
                const int r0 = bm + wm0 + im * 16 + (lane >> 2);
                float2 o0 = make_float2(d[im][jt][0] + bb.x, d[im][jt][1] + bb.y);
                float2 o1 = make_float2(d[im][jt][2] + bb.x, d[im][jt][3] + bb.y);
                *reinterpret_cast<float2*>(C + (size_t)r0 * AD + c0)       = o0;
                *reinterpret_cast<float2*>(C + (size_t)(r0 + 8) * AD + c0) = o1;
            }
        }
    } else {
        // fp16 head-plane epilogue: [(b*NH+h)][L][64]
#pragma unroll
        for (int jt = 0; jt < 4; ++jt) {
            const int c0 = bn + wn0 + jt * 8 + 2 * (lane & 3);
            float2 bb = *reinterpret_cast<const float2*>(bias + c0);
            const int hh = c0 >> 6, dd = c0 & 63;
#pragma unroll
            for (int im = 0; im < 4; ++im) {
                const int r0 = bm + wm0 + im * 16 + (lane >> 2);
#pragma unroll
                for (int half = 0; half < 2; ++half) {
                    const int r = r0 + half * 8;
                    float v0 = (d[im][jt][half * 2 + 0] + bb.x) * oscale;
                    float v1 = (d[im][jt][half * 2 + 1] + bb.y) * oscale;
                    size_t addr = ((size_t)((r >> 11) * NH + hh) * LL + (r & 2047)) * HD + dd;
                    *reinterpret_cast<uint32_t*>(outH + addr) =
                        pack_h2(__float2half_rn(v0), __float2half_rn(v1));
                }
            }
        }
    }
}

// Fused QKV wrapper: blockIdx.z in {0,1,2} selects the projection.
struct QkvArgs {
    const __half* A;
    const __half* W;
    const float*  bias[3];
    __half*       outH;
};

__global__ __launch_bounds__(256, 2)
void gemm_qkv(QkvArgs a)
{
    extern __shared__ char smem[];
    const int z = blockIdx.z;
    const float oscale = (z == 0) ? 0.125f : 1.0f;
    gemm_body(a.A + (size_t)z * MM * AD,
              a.W + (size_t)z * AD * AD,
              a.bias[z],
              nullptr,
              a.outH + (size_t)z * MM * AD,
              oscale, smem);
}

__global__ __launch_bounds__(256, 2)
void gemm_out(const __half* __restrict__ A, const __half* __restrict__ Bt,
              const float* __restrict__ bias, float* __restrict__ C)
{
    extern __shared__ char smem[];
    gemm_body(A, Bt, bias, C, nullptr, 1.0f, smem);
}

// ---------------------------------------------------------------------------
// fp16 mma flash attention — occupancy build.
// CTA = 64 q-rows x (head, batch); 128 threads / 4 warps; warp owns 16 rows.
// KV chunks of 64 rows (S regs halved), V fragments streamed (not cached),
// __launch_bounds__(128,4): <=128 regs -> 16 warps/SM (was 12 at 168 regs).
// smem: Q 8KB + 2 stages x (K 8KB + V 8KB) = 40KB -> 4 CTAs fit easily.
// ---------------------------------------------------------------------------
#define AT_Q    0
#define AT_BUF  8192                    // stage s at + s*16384 ; K +0, V +8192
#define AT_SMEM (8192 + 2*16384)        // 40960
#define AT_NC   (LL / 64)               // 32 chunks

__device__ __forceinline__ void at_load64(uint32_t sb, uint32_t soff,
                                          const __half* __restrict__ g,
                                          size_t pbase, int row0, int tid)
{
#pragma unroll
    for (int i = 0; i < 4; ++i) {
        int idx = i * 128 + tid;
        int r = idx >> 3, seg = idx & 7;
        const char* src = (const char*)(g + pbase + (size_t)(row0 + r) * HD) + seg * 16;
        uint32_t dst = sb + soff + r * 128 + ((seg * 16) ^ ((r & 7) * 16));
        asm volatile("cp.async.cg.shared.global [%0], [%1], 16;" :: "r"(dst), "l"(src));
    }
}

__global__ __launch_bounds__(128, 4)
void attn_mma(const __half* __restrict__ Qh,
              const __half* __restrict__ Kh,
              const __half* __restrict__ Vh,
              __half* __restrict__ Oatt)
{
    extern __shared__ char smem[];
    const uint32_t sb = smem_u32(smem);
    const int tid  = threadIdx.x;
    const int warp = tid >> 5;
    const int lane = tid & 31;
    const int gidr = lane >> 2;
    const int tg   = lane & 3;

    const int qt = blockIdx.x, h = blockIdx.y, b = blockIdx.z;
    const size_t pbase = (size_t)(b * NH + h) * LL * HD;
    const int q0 = qt * 64;

    // prologue: Q, chunk0, chunk1 (three cp.async groups)
    at_load64(sb, AT_Q, Qh, pbase, q0, tid);
    CP_COMMIT();
    at_load64(sb, AT_BUF,        Kh, pbase, 0, tid);
    at_load64(sb, AT_BUF + 8192, Vh, pbase, 0, tid);
    CP_COMMIT();
    at_load64(sb, AT_BUF + 16384, Kh, pbase, 64, tid);
    at_load64(sb, AT_BUF + 24576, Vh, pbase, 64, tid);
    CP_COMMIT();

    const uint32_t a_row = 16 * warp + (lane & 15);
    const uint32_t a_off = a_row * 128;
    const uint32_t a_sw  = (a_row & 7) * 16;
    const uint32_t a_kb  = (lane >> 4) * 16;
    const uint32_t b_rowb = (lane & 7) + ((lane >> 4) << 3);
    const uint32_t b_kb   = ((lane >> 3) & 1) * 16;
    const uint32_t v_rowb = (lane & 15);
    const uint32_t v_cb   = (lane >> 4) * 16;

    float m0 = -1e30f, m1 = -1e30f, l0 = 0.f, l1 = 0.f;
    float O[8][4];
#pragma unroll
    for (int j = 0; j < 8; ++j)
#pragma unroll
        for (int q = 0; q < 4; ++q) O[j][q] = 0.f;

    for (int ci = 0; ci < AT_NC; ++ci) {
        if (ci < AT_NC - 1) { CP_WAIT(1); } else { CP_WAIT(0); }
        __syncthreads();

        const uint32_t kh_ = sb + AT_BUF + (ci & 1) * 16384;
        const uint32_t vh_ = kh_ + 8192;

        // ---- S = Q K^T over 64 kv cols ----
        float s[8][4];
#pragma unroll
        for (int j = 0; j < 8; ++j)
#pragma unroll
            for (int q = 0; q < 4; ++q) s[j][q] = 0.f;

#pragma unroll
        for (int ks = 0; ks < 4; ++ks) {
            const uint32_t kb = ks * 32;
            uint32_t af[4];
            ldm_x4(af[0], af[1], af[2], af[3], sb + AT_Q + a_off + ((kb + a_kb) ^ a_sw));
#pragma unroll
            for (int jj = 0; jj < 4; ++jj) {
                uint32_t row = 16 * jj + b_rowb;
                uint32_t r0, r1, r2, r3;
                ldm_x4(r0, r1, r2, r3, kh_ + row * 128 + ((kb + b_kb) ^ ((row & 7) * 16)));
                mma16816(s[2 * jj],     af, r0, r1);
                mma16816(s[2 * jj + 1], af, r2, r3);
            }
        }

        // ---- online softmax (quad shuffles span the 64 kv cols) ----
        float cm0 = -1e30f, cm1 = -1e30f;
#pragma unroll
        for (int j = 0; j < 8; ++j) {
            cm0 = fmaxf(cm0, fmaxf(s[j][0], s[j][1]));
            cm1 = fmaxf(cm1, fmaxf(s[j][2], s[j][3]));
        }
        cm0 = fmaxf(cm0, __shfl_xor_sync(0xffffffffu, cm0, 1));
        cm0 = fmaxf(cm0, __shfl_xor_sync(0xffffffffu, cm0, 2));
        cm1 = fmaxf(cm1, __shfl_xor_sync(0xffffffffu, cm1, 1));
        cm1 = fmaxf(cm1, __shfl_xor_sync(0xffffffffu, cm1, 2));
        const float mn0 = fmaxf(m0, cm0);
        const float mn1 = fmaxf(m1, cm1);
        const float corr0 = __expf(m0 - mn0);
        const float corr1 = __expf(m1 - mn1);
        m0 = mn0; m1 = mn1;
#pragma unroll
        for (int j = 0; j < 8; ++j) {
            O[j][0] *= corr0; O[j][1] *= corr0;
            O[j][2] *= corr1; O[j][3] *= corr1;
        }
        l0 *= corr0; l1 *= corr1;

        float rs0 = 0.f, rs1 = 0.f;

        // ---- PV over 64 kv rows: P fp16 in regs, V frags streamed ----
#pragma unroll
        for (int kk = 0; kk < 4; ++kk) {
            float p00 = __expf(s[2*kk][0]   - mn0);
            float p01 = __expf(s[2*kk][1]   - mn0);
            float p02 = __expf(s[2*kk][2]   - mn1);
            float p03 = __expf(s[2*kk][3]   - mn1);
            float p10 = __expf(s[2*kk+1][0] - mn0);
            float p11 = __expf(s[2*kk+1][1] - mn0);
            float p12 = __expf(s[2*kk+1][2] - mn1);
            float p13 = __expf(s[2*kk+1][3] - mn1);
            rs0 += (p00 + p01) + (p10 + p11);
            rs1 += (p02 + p03) + (p12 + p13);

            uint32_t ah[4];
            ah[0] = pack_h2(__float2half_rn(p00), __float2half_rn(p01));
            ah[1] = pack_h2(__float2half_rn(p02), __float2half_rn(p03));
            ah[2] = pack_h2(__float2half_rn(p10), __float2half_rn(p11));
            ah[3] = pack_h2(__float2half_rn(p12), __float2half_rn(p13));

            const uint32_t vrow = 16 * kk + v_rowb;
            const uint32_t vsw  = (vrow & 7) * 16;
            const uint32_t vaddr = vh_ + vrow * 128;
#pragma unroll
            for (int nb = 0; nb < 4; ++nb) {
                uint32_t r0, r1, r2, r3;
                ldm_x4_t(r0, r1, r2, r3, vaddr + (((uint32_t)(nb * 32) + v_cb) ^ vsw));
                mma16816(O[2 * nb],     ah, r0, r1);
                mma16816(O[2 * nb + 1], ah, r2, r3);
            }
        }

        rs0 += __shfl_xor_sync(0xffffffffu, rs0, 1);
        rs0 += __shfl_xor_sync(0xffffffffu, rs0, 2);
        rs1 += __shfl_xor_sync(0xffffffffu, rs1, 1);
        rs1 += __shfl_xor_sync(0xffffffffu, rs1, 2);
        l0 += rs0; l1 += rs1;

        __syncthreads();   // all warps done reading buf (ci&1)
        if (ci + 2 < AT_NC) {
            uint32_t bb = AT_BUF + (ci & 1) * 16384;
            int row0 = (ci + 2) * 64;
            at_load64(sb, bb,        Kh, pbase, row0, tid);
            at_load64(sb, bb + 8192, Vh, pbase, row0, tid);
            CP_COMMIT();
        }
    }

    // ---- epilogue: normalize, write fp16 into g_ao [M,1024] ----
    const float inv0 = 1.f / l0;
    const float inv1 = 1.f / l1;
    const int colb = h * HD + 2 * tg;
#pragma unroll
    for (int jf = 0; jf < 8; ++jf) {
#pragma unroll
        for (int half = 0; half < 2; ++half) {
            const int r = 16 * warp + gidr + half * 8;
            const float inv = half ? inv1 : inv0;
            float v0 = O[jf][half * 2 + 0] * inv;
            float v1 = O[jf][half * 2 + 1] * inv;
            size_t addr = (size_t)(b * LL + q0 + r) * AD + colb + 8 * jf;
            *reinterpret_cast<uint32_t*>(Oatt + addr) =
                pack_h2(__float2half_rn(v0), __float2half_rn(v1));
        }
    }
}

// ---------------------------------------------------------------------------
// Launch: 5 kernels total
// ---------------------------------------------------------------------------
extern "C" void kernel_launch(void* const* d_in, const int* in_sizes, int n_in,
                              void* d_out, int out_size)
{
    const float* query = (const float*)d_in[0];
    const float* key   = (const float*)d_in[1];
    const float* value = (const float*)d_in[2];
    const float* Wq = (const float*)d_in[3];
    const float* bq = (const float*)d_in[4];
    const float* Wk = (const float*)d_in[5];
    const float* bk = (const float*)d_in[6];
    const float* Wv = (const float*)d_in[7];
    const float* bv = (const float*)d_in[8];
    const float* Wo = (const float*)d_in[9];
    const float* bo = (const float*)d_in[10];
    float* out = (float*)d_out;

    __half *pacts, *pwt, *pheads, *pao;
    cudaGetSymbolAddress((void**)&pacts,  g_acts);
    cudaGetSymbolAddress((void**)&pwt,    g_wt);
    cudaGetSymbolAddress((void**)&pheads, g_heads);
    cudaGetSymbolAddress((void**)&pao,    g_ao);

    cudaFuncSetAttribute(gemm_qkv, cudaFuncAttributeMaxDynamicSharedMemorySize, G_SMEM);
    cudaFuncSetAttribute(gemm_out, cudaFuncAttributeMaxDynamicSharedMemorySize, G_SMEM);
    cudaFuncSetAttribute(attn_mma, cudaFuncAttributeMaxDynamicSharedMemorySize, AT_SMEM);

    // 1) all weight transposes
    dim3 wgrid(32, 32, 4), wblk(32, 8);
    conv_wt4<<<wgrid, wblk>>>(Wq, Wk, Wv, Wo, pwt);

    // 2) all activation conversions
    dim3 cgrid(MM, 3);
    conv_act3<<<cgrid, 256>>>(query, key, value, pacts);

    // 3) fused QKV projection GEMM
    QkvArgs qa;
    qa.A = pacts; qa.W = pwt; qa.outH = pheads;
    qa.bias[0] = bq; qa.bias[1] = bk; qa.bias[2] = bv;
    dim3 ggrid(AD / 128, MM / 128, 3);   // (8, 64, 3)
    gemm_qkv<<<ggrid, 256, G_SMEM>>>(qa);

    // 4) attention
    dim3 agrid(LL / 64, NH, BB);         // (32, 16, 4)
    attn_mma<<<agrid, 128, AT_SMEM>>>(pheads,
                                      pheads + (size_t)MM * AD,
                                      pheads + 2 * (size_t)MM * AD,
                                      pao);

    // 5) output projection
    dim3 ogrid(AD / 128, MM / 128);      // (8, 64)
    gemm_out<<<ogrid, 256, G_SMEM>>>(pao, pwt + 3 * (size_t)AD * AD, bo, out);
}

// round 11
// speedup vs baseline: 1.5432x; 1.5432x over previous
#include <cuda_runtime.h>
#include <cuda_fp16.h>
#include <cstdint>

// Problem constants
#define BB   4
#define LL   2048
#define AD   1024
#define NH   16
#define HD   64
#define MM   (BB*LL)   // 8192

// ---------------------------------------------------------------------------
// Scratch (device globals)
// ---------------------------------------------------------------------------
__device__ __half g_acts [3 * MM * AD];    // fp16 activations q|k|v
__device__ __half g_wt   [4 * AD * AD];    // weights^T fp16 (q,k,v,o)
__device__ __half g_heads[3 * MM * AD];    // head planes Q(prescaled)|K|V
__device__ __half g_ao   [MM * AD];        // attention output fp16 [M,1024]

// ---------------------------------------------------------------------------
// Helpers (plain sm_103-legal: cp.async, ldmatrix, mma.sync)
// ---------------------------------------------------------------------------
__device__ __forceinline__ uint32_t smem_u32(const void* p) {
    uint32_t a;
    asm("{ .reg .u64 t; cvta.to.shared.u64 t, %1; cvt.u32.u64 %0, t; }" : "=r"(a) : "l"(p));
    return a;
}
#define CP_COMMIT()  asm volatile("cp.async.commit_group;" ::: "memory")
#define CP_WAIT(n)   asm volatile("cp.async.wait_group %0;" :: "n"(n) : "memory")

__device__ __forceinline__ uint32_t pack_h2(__half a, __half b) {
    return (uint32_t)__half_as_ushort(a) | ((uint32_t)__half_as_ushort(b) << 16);
}
__device__ __forceinline__ void ldm_x4(uint32_t& r0, uint32_t& r1, uint32_t& r2, uint32_t& r3,
                                       uint32_t addr) {
    asm volatile("ldmatrix.sync.aligned.m8n8.x4.shared.b16 {%0,%1,%2,%3}, [%4];"
                 : "=r"(r0), "=r"(r1), "=r"(r2), "=r"(r3) : "r"(addr));
}
__device__ __forceinline__ void ldm_x4_t(uint32_t& r0, uint32_t& r1, uint32_t& r2, uint32_t& r3,
                                         uint32_t addr) {
    asm volatile("ldmatrix.sync.aligned.m8n8.x4.trans.shared.b16 {%0,%1,%2,%3}, [%4];"
                 : "=r"(r0), "=r"(r1), "=r"(r2), "=r"(r3) : "r"(addr));
}
__device__ __forceinline__ void mma16816(float* d, const uint32_t* a, uint32_t b0, uint32_t b1) {
    asm volatile(
        "mma.sync.aligned.m16n8k16.row.col.f32.f16.f16.f32 "
        "{%0,%1,%2,%3}, {%4,%5,%6,%7}, {%8,%9}, {%0,%1,%2,%3};"
        : "+f"(d[0]), "+f"(d[1]), "+f"(d[2]), "+f"(d[3])
        : "r"(a[0]), "r"(a[1]), "r"(a[2]), "r"(a[3]), "r"(b0), "r"(b1));
}

// ---------------------------------------------------------------------------
// conv_act fused: 3 inputs fp32 [M,1024] -> fp16, selected by blockIdx.y
// ---------------------------------------------------------------------------
__global__ void conv_act3(const float* __restrict__ X0, const float* __restrict__ X1,
                          const float* __restrict__ X2, __half* __restrict__ Y)
{
    const int z = blockIdx.y;
    const float* X = (z == 0) ? X0 : (z == 1) ? X1 : X2;
    int m = blockIdx.x;
    int c = threadIdx.x * 4;
    float4 v = *reinterpret_cast<const float4*>(X + (size_t)m * AD + c);
    uint2 o;
    o.x = pack_h2(__float2half_rn(v.x), __float2half_rn(v.y));
    o.y = pack_h2(__float2half_rn(v.z), __float2half_rn(v.w));
    *reinterpret_cast<uint2*>(Y + (size_t)z * MM * AD + (size_t)m * AD + c) = o;
}

// ---------------------------------------------------------------------------
// conv_wt fused: 4 weights W[K][N] fp32 -> Wt[N][K] fp16, selected by blockIdx.z
// ---------------------------------------------------------------------------
__global__ void conv_wt4(const float* __restrict__ W0, const float* __restrict__ W1,
                         const float* __restrict__ W2, const float* __restrict__ W3,
                         __half* __restrict__ WtBase)
{
    __shared__ float s[32][33];
    const int z = blockIdx.z;
    const float* W = (z == 0) ? W0 : (z == 1) ? W1 : (z == 2) ? W2 : W3;
    __half* Wt = WtBase + (size_t)z * AD * AD;
    int n0 = blockIdx.x * 32;
    int k0 = blockIdx.y * 32;
    int tx = threadIdx.x, ty = threadIdx.y;   // (32, 8)
#pragma unroll
    for (int i = 0; i < 4; ++i)
        s[ty + 8 * i][tx] = W[(size_t)(k0 + ty + 8 * i) * AD + n0 + tx];
    __syncthreads();
#pragma unroll
    for (int i = 0; i < 4; ++i) {
        int n = n0 + ty + 8 * i;
        int k = k0 + tx;
        Wt[(size_t)n * AD + k] = __float2half_rn(s[tx][ty + 8 * i]);
    }
}

// ---------------------------------------------------------------------------
// fp16 mma GEMM core (unchanged, proven).
// ---------------------------------------------------------------------------
#define GK_NC 16
#define SA0   0
#define SA1   16384
#define SB0   32768
#define SB1   49152
#define G_SMEM 65536

__device__ __forceinline__ void load_tile_cp(uint32_t sbase, uint32_t soff,
                                             const __half* __restrict__ g,
                                             int row0, int kc, int tid)
{
#pragma unroll
    for (int i = 0; i < 4; ++i) {
        int idx = i * 256 + tid;
        int r = idx >> 3, seg = idx & 7;
        const char* src = (const char*)g + ((size_t)(row0 + r) * AD + kc) * 2 + seg * 16;
        uint32_t dst = sbase + soff + r * 128 + ((seg * 16) ^ ((r & 7) * 16));
        asm volatile("cp.async.cg.shared.global [%0], [%1], 16;" :: "r"(dst), "l"(src));
    }
}

__device__ __forceinline__ void gemm_body(const __half* __restrict__ A,
                                          const __half* __restrict__ Bt,
                                          const float* __restrict__ bias,
                                          float* __restrict__ C,
                                          __half* __restrict__ outH,
                                          float oscale,
                                          char* smem)
{
    const uint32_t sbase = smem_u32(smem);
    const int tid  = threadIdx.x;
    const int warp = tid >> 5;
    const int lane = tid & 31;
    const int bn = blockIdx.x * 128;
    const int bm = blockIdx.y * 128;

    const int wm0 = (warp >> 2) * 64;
    const int wn0 = (warp & 3) * 32;

    float d[4][4][4];
#pragma unroll
    for (int im = 0; im < 4; ++im)
#pragma unroll
        for (int jt = 0; jt < 4; ++jt)
#pragma unroll
            for (int q = 0; q < 4; ++q) d[im][jt][q] = 0.f;

    uint32_t a_rb[4], a_sw[4];
#pragma unroll
    for (int im = 0; im < 4; ++im) {
        int row = wm0 + im * 16 + (lane & 15);
        a_rb[im] = row * 128;
        a_sw[im] = (row & 7) * 16;
    }
    const uint32_t a_kb = (lane >> 4) * 16;
    uint32_t b_rb[2], b_sw[2];
#pragma unroll
    for (int jn = 0; jn < 2; ++jn) {
        int row = wn0 + jn * 16 + (lane & 7) + ((lane >> 4) << 3);
        b_rb[jn] = row * 128;
        b_sw[jn] = (row & 7) * 16;
    }
    const uint32_t b_kb = ((lane >> 3) & 1) * 16;

    load_tile_cp(sbase, SA0, A,  bm, 0, tid);
    load_tile_cp(sbase, SB0, Bt, bn, 0, tid);
    CP_COMMIT();

    for (int i = 0; i < GK_NC; ++i) {
        const uint32_t aoff = (i & 1) ? SA1 : SA0;
        const uint32_t boff = (i & 1) ? SB1 : SB0;
        if (i + 1 < GK_NC) {
            load_tile_cp(sbase, (i & 1) ? SA0 : SA1, A,  bm, (i + 1) * 64, tid);
            load_tile_cp(sbase, (i & 1) ? SB0 : SB1, Bt, bn, (i + 1) * 64, tid);
            CP_COMMIT();
            CP_WAIT(1);
        } else {
            CP_WAIT(0);
        }
        __syncthreads();

#pragma unroll
        for (int ks = 0; ks < 4; ++ks) {
            const uint32_t kb = ks * 32;
            uint32_t af[4][4];
#pragma unroll
            for (int im = 0; im < 4; ++im)
                ldm_x4(af[im][0], af[im][1], af[im][2], af[im][3],
                       sbase + aoff + a_rb[im] + ((kb + a_kb) ^ a_sw[im]));
            uint32_t bf[4][2];
#pragma unroll
            for (int jn = 0; jn < 2; ++jn) {
                uint32_t r0, r1, r2, r3;
                ldm_x4(r0, r1, r2, r3,
                       sbase + boff + b_rb[jn] + ((kb + b_kb) ^ b_sw[jn]));
                bf[jn * 2][0] = r0; bf[jn * 2][1] = r1;
                bf[jn * 2 + 1][0] = r2; bf[jn * 2 + 1][1] = r3;
            }
#pragma unroll
            for (int im = 0; im < 4; ++im)
#pragma unroll
                for (int jt = 0; jt < 4; ++jt)
                    mma16816(d[im][jt], af[im], bf[jt][0], bf[jt][1]);
        }
        __syncthreads();
    }

    if (outH == nullptr) {
#pragma unroll
        for (int jt = 0; jt < 4; ++jt) {
            const int c0 = bn + wn0 + jt * 8 + 2 * (lane & 3);
            float2 bb = *reinterpret_cast<const float2*>(bias + c0);
#pragma unroll
            for (int im = 0; im < 4; ++im) {
                const int r0 = bm + wm0 + im * 16 + (lane >> 2);
                float2 o0 = make_float2(d[im][jt][0] + bb.x, d[im][jt][1] + bb.y);
                float2 o1 = make_float2(d[im][jt][2] + bb.x, d[im][jt][3] + bb.y);
                *reinterpret_cast<float2*>(C + (size_t)r0 * AD + c0)       = o0;
                *reinterpret_cast<float2*>(C + (size_t)(r0 + 8) * AD + c0) = o1;
            }
        }
    } else {
        // fp16 head-plane epilogue: [(b*NH+h)][L][64]
#pragma unroll
        for (int jt = 0; jt < 4; ++jt) {
            const int c0 = bn + wn0 + jt * 8 + 2 * (lane & 3);
            float2 bb = *reinterpret_cast<const float2*>(bias + c0);
            const int hh = c0 >> 6, dd = c0 & 63;
#pragma unroll
            for (int im = 0; im < 4; ++im) {
                const int r0 = bm + wm0 + im * 16 + (lane >> 2);
#pragma unroll
                for (int half = 0; half < 2; ++half) {
                    const int r = r0 + half * 8;
                    float v0 = (d[im][jt][half * 2 + 0] + bb.x) * oscale;
                    float v1 = (d[im][jt][half * 2 + 1] + bb.y) * oscale;
                    size_t addr = ((size_t)((r >> 11) * NH + hh) * LL + (r & 2047)) * HD + dd;
                    *reinterpret_cast<uint32_t*>(outH + addr) =
                        pack_h2(__float2half_rn(v0), __float2half_rn(v1));
                }
            }
        }
    }
}

// Fused QKV wrapper: blockIdx.z in {0,1,2} selects the projection.
struct QkvArgs {
    const __half* A;
    const __half* W;
    const float*  bias[3];
    __half*       outH;
};

// Q prescale folds softmax scale AND log2(e) so attention can use exp2f.
#define Q_PRESCALE (0.125f * 1.4426950408889634f)

__global__ __launch_bounds__(256, 2)
void gemm_qkv(QkvArgs a)
{
    extern __shared__ char smem[];
    const int z = blockIdx.z;
    const float oscale = (z == 0) ? Q_PRESCALE : 1.0f;
    gemm_body(a.A + (size_t)z * MM * AD,
              a.W + (size_t)z * AD * AD,
              a.bias[z],
              nullptr,
              a.outH + (size_t)z * MM * AD,
              oscale, smem);
}

__global__ __launch_bounds__(256, 2)
void gemm_out(const __half* __restrict__ A, const __half* __restrict__ Bt,
              const float* __restrict__ bias, float* __restrict__ C)
{
    extern __shared__ char smem[];
    gemm_body(A, Bt, bias, C, nullptr, 1.0f, smem);
}

// ---------------------------------------------------------------------------
// fp16 mma flash attention — R9 structure (proven 217us) + micro-opts:
//  * exp2f instead of __expf (log2e prefolded into Q)
//  * per-thread partial l accumulation; quad reduction deferred to epilogue
// CTA = 64 q-rows; 128 threads / 4 warps; warp owns 16 rows; KV chunks 128.
// ---------------------------------------------------------------------------
#define AT_Q   0
#define AT_BUF 8192                     // + buf*32768 ; Kh at +0, Vh at +16384
#define AT_SMEM (8192 + 2*32768)        // 73728

__device__ __forceinline__ void at_load_plane(uint32_t sb, uint32_t soff,
                                              const __half* __restrict__ g,
                                              size_t pbase, int row0, int nrows, int tid)
{
    const int iters = nrows / 16;
#pragma unroll
    for (int i = 0; i < 8; ++i) {
        if (i >= iters) break;
        int idx = i * 128 + tid;
        int r = idx >> 3, seg = idx & 7;
        const char* src = (const char*)(g + pbase + (size_t)(row0 + r) * HD) + seg * 16;
        uint32_t dst = sb + soff + r * 128 + ((seg * 16) ^ ((r & 7) * 16));
        asm volatile("cp.async.cg.shared.global [%0], [%1], 16;" :: "r"(dst), "l"(src));
    }
}

__global__ __launch_bounds__(128, 3)
void attn_mma(const __half* __restrict__ Qh,
              const __half* __restrict__ Kh,
              const __half* __restrict__ Vh,
              __half* __restrict__ Oatt)
{
    extern __shared__ char smem[];
    const uint32_t sb = smem_u32(smem);
    const int tid  = threadIdx.x;
    const int warp = tid >> 5;
    const int lane = tid & 31;
    const int gidr = lane >> 2;
    const int tg   = lane & 3;

    const int qt = blockIdx.x, h = blockIdx.y, b = blockIdx.z;
    const size_t pbase = (size_t)(b * NH + h) * LL * HD;
    const int q0 = qt * 64;

    at_load_plane(sb, AT_Q, Qh, pbase, q0, 64, tid);
    CP_COMMIT();
    at_load_plane(sb, AT_BUF,         Kh, pbase, 0, 128, tid);
    at_load_plane(sb, AT_BUF + 16384, Vh, pbase, 0, 128, tid);
    CP_COMMIT();
    at_load_plane(sb, AT_BUF + 32768, Kh, pbase, 128, 128, tid);
    at_load_plane(sb, AT_BUF + 49152, Vh, pbase, 128, 128, tid);
    CP_COMMIT();

    const uint32_t a_row = 16 * warp + (lane & 15);
    const uint32_t a_off = a_row * 128;
    const uint32_t a_sw  = (a_row & 7) * 16;
    const uint32_t a_kb  = (lane >> 4) * 16;
    const uint32_t b_rowb = (lane & 7) + ((lane >> 4) << 3);
    const uint32_t b_kb   = ((lane >> 3) & 1) * 16;
    const uint32_t v_rowb = (lane & 15);
    const uint32_t v_cb   = (lane >> 4) * 16;

    float m0 = -1e30f, m1 = -1e30f, l0 = 0.f, l1 = 0.f;   // l: per-thread partials
    float O[8][4];
#pragma unroll
    for (int j = 0; j < 8; ++j)
#pragma unroll
        for (int q = 0; q < 4; ++q) O[j][q] = 0.f;

    for (int ci = 0; ci < 16; ++ci) {
        if (ci < 15) { CP_WAIT(1); } else { CP_WAIT(0); }
        __syncthreads();

        const uint32_t kh_ = sb + AT_BUF + (ci & 1) * 32768;
        const uint32_t vh_ = kh_ + 16384;

        // ---- S = Q K^T (values are logits * log2e) ----
        float s[16][4];
#pragma unroll
        for (int j = 0; j < 16; ++j)
#pragma unroll
            for (int q = 0; q < 4; ++q) s[j][q] = 0.f;

#pragma unroll
        for (int ks = 0; ks < 4; ++ks) {
            const uint32_t kb = ks * 32;
            uint32_t af[4];
            ldm_x4(af[0], af[1], af[2], af[3], sb + AT_Q + a_off + ((kb + a_kb) ^ a_sw));
#pragma unroll
            for (int jj = 0; jj < 8; ++jj) {
                uint32_t row = 16 * jj + b_rowb;
                uint32_t r0, r1, r2, r3;
                ldm_x4(r0, r1, r2, r3, kh_ + row * 128 + ((kb + b_kb) ^ ((row & 7) * 16)));
                mma16816(s[2 * jj],     af, r0, r1);
                mma16816(s[2 * jj + 1], af, r2, r3);
            }
        }

        // ---- online softmax in base-2 ----
        float cm0 = -1e30f, cm1 = -1e30f;
#pragma unroll
        for (int j = 0; j < 16; ++j) {
            cm0 = fmaxf(cm0, fmaxf(s[j][0], s[j][1]));
            cm1 = fmaxf(cm1, fmaxf(s[j][2], s[j][3]));
        }
        cm0 = fmaxf(cm0, __shfl_xor_sync(0xffffffffu, cm0, 1));
        cm0 = fmaxf(cm0, __shfl_xor_sync(0xffffffffu, cm0, 2));
        cm1 = fmaxf(cm1, __shfl_xor_sync(0xffffffffu, cm1, 1));
        cm1 = fmaxf(cm1, __shfl_xor_sync(0xffffffffu, cm1, 2));
        const float mn0 = fmaxf(m0, cm0);
        const float mn1 = fmaxf(m1, cm1);
        const float corr0 = exp2f(m0 - mn0);
        const float corr1 = exp2f(m1 - mn1);
        m0 = mn0; m1 = mn1;
#pragma unroll
        for (int j = 0; j < 8; ++j) {
            O[j][0] *= corr0; O[j][1] *= corr0;
            O[j][2] *= corr1; O[j][3] *= corr1;
        }
        l0 *= corr0; l1 *= corr1;   // per-thread partials (corr is quad-uniform)

        // ---- PV: P fp16 in regs, V B-fragments via ldmatrix.trans ----
#pragma unroll
        for (int kk = 0; kk < 8; ++kk) {
            float p00 = exp2f(s[2*kk][0]   - mn0);
            float p01 = exp2f(s[2*kk][1]   - mn0);
            float p02 = exp2f(s[2*kk][2]   - mn1);
            float p03 = exp2f(s[2*kk][3]   - mn1);
            float p10 = exp2f(s[2*kk+1][0] - mn0);
            float p11 = exp2f(s[2*kk+1][1] - mn0);
            float p12 = exp2f(s[2*kk+1][2] - mn1);
            float p13 = exp2f(s[2*kk+1][3] - mn1);
            l0 += (p00 + p01) + (p10 + p11);
            l1 += (p02 + p03) + (p12 + p13);

            uint32_t ah[4];
            ah[0] = pack_h2(__float2half_rn(p00), __float2half_rn(p01));
            ah[1] = pack_h2(__float2half_rn(p02), __float2half_rn(p03));
            ah[2] = pack_h2(__float2half_rn(p10), __float2half_rn(p11));
            ah[3] = pack_h2(__float2half_rn(p12), __float2half_rn(p13));

            const uint32_t vrow = 16 * kk + v_rowb;
            const uint32_t vsw  = (vrow & 7) * 16;
            const uint32_t vaddr = vh_ + vrow * 128;
#pragma unroll
            for (int nb = 0; nb < 4; ++nb) {
                uint32_t r0, r1, r2, r3;
                ldm_x4_t(r0, r1, r2, r3, vaddr + (((uint32_t)(nb * 32) + v_cb) ^ vsw));
                mma16816(O[2 * nb],     ah, r0, r1);
                mma16816(O[2 * nb + 1], ah, r2, r3);
            }
        }

        __syncthreads();   // all warps done reading buf (ci&1)
        if (ci + 2 < 16) {
            uint32_t bb = AT_BUF + (ci & 1) * 32768;
            int row0 = (ci + 2) * 128;
            at_load_plane(sb, bb,         Kh, pbase, row0, 128, tid);
            at_load_plane(sb, bb + 16384, Vh, pbase, row0, 128, tid);
            CP_COMMIT();
        }
    }

    // ---- epilogue: quad-reduce l (deferred), normalize, store fp16 ----
    l0 += __shfl_xor_sync(0xffffffffu, l0, 1);
    l0 += __shfl_xor_sync(0xffffffffu, l0, 2);
    l1 += __shfl_xor_sync(0xffffffffu, l1, 1);
    l1 += __shfl_xor_sync(0xffffffffu, l1, 2);
    const float inv0 = 1.f / l0;
    const float inv1 = 1.f / l1;
    const int colb = h * HD + 2 * tg;
#pragma unroll
    for (int jf = 0; jf < 8; ++jf) {
#pragma unroll
        for (int half = 0; half < 2; ++half) {
            const int r = 16 * warp + gidr + half * 8;
            const float inv = half ? inv1 : inv0;
            float v0 = O[jf][half * 2 + 0] * inv;
            float v1 = O[jf][half * 2 + 1] * inv;
            size_t addr = (size_t)(b * LL + q0 + r) * AD + colb + 8 * jf;
            *reinterpret_cast<uint32_t*>(Oatt + addr) =
                pack_h2(__float2half_rn(v0), __float2half_rn(v1));
        }
    }
}

// ---------------------------------------------------------------------------
// Launch: 5 kernels total
// ---------------------------------------------------------------------------
extern "C" void kernel_launch(void* const* d_in, const int* in_sizes, int n_in,
                              void* d_out, int out_size)
{
    const float* query = (const float*)d_in[0];
    const float* key   = (const float*)d_in[1];
    const float* value = (const float*)d_in[2];
    const float* Wq = (const float*)d_in[3];
    const float* bq = (const float*)d_in[4];
    const float* Wk = (const float*)d_in[5];
    const float* bk = (const float*)d_in[6];
    const float* Wv = (const float*)d_in[7];
    const float* bv = (const float*)d_in[8];
    const float* Wo = (const float*)d_in[9];
    const float* bo = (const float*)d_in[10];
    float* out = (float*)d_out;

    __half *pacts, *pwt, *pheads, *pao;
    cudaGetSymbolAddress((void**)&pacts,  g_acts);
    cudaGetSymbolAddress((void**)&pwt,    g_wt);
    cudaGetSymbolAddress((void**)&pheads, g_heads);
    cudaGetSymbolAddress((void**)&pao,    g_ao);

    cudaFuncSetAttribute(gemm_qkv, cudaFuncAttributeMaxDynamicSharedMemorySize, G_SMEM);
    cudaFuncSetAttribute(gemm_out, cudaFuncAttributeMaxDynamicSharedMemorySize, G_SMEM);
    cudaFuncSetAttribute(attn_mma, cudaFuncAttributeMaxDynamicSharedMemorySize, AT_SMEM);

    // 1) all weight transposes
    dim3 wgrid(32, 32, 4), wblk(32, 8);
    conv_wt4<<<wgrid, wblk>>>(Wq, Wk, Wv, Wo, pwt);

    // 2) all activation conversions
    dim3 cgrid(MM, 3);
    conv_act3<<<cgrid, 256>>>(query, key, value, pacts);

    // 3) fused QKV projection GEMM
    QkvArgs qa;
    qa.A = pacts; qa.W = pwt; qa.outH = pheads;
    qa.bias[0] = bq; qa.bias[1] = bk; qa.bias[2] = bv;
    dim3 ggrid(AD / 128, MM / 128, 3);   // (8, 64, 3)
    gemm_qkv<<<ggrid, 256, G_SMEM>>>(qa);

    // 4) attention
    dim3 agrid(LL / 64, NH, BB);         // (32, 16, 4)
    attn_mma<<<agrid, 128, AT_SMEM>>>(pheads,
                                      pheads + (size_t)MM * AD,
                                      pheads + 2 * (size_t)MM * AD,
                                      pao);

    // 5) output projection
    dim3 ogrid(AD / 128, MM / 128);      // (8, 64)
    gemm_out<<<ogrid, 256, G_SMEM>>>(pao, pwt + 3 * (size_t)AD * AD, bo, out);
}

// round 12
// speedup vs baseline: 1.6364x; 1.0604x over previous
#include <cuda_runtime.h>
#include <cuda_fp16.h>
#include <cstdint>

// Problem constants
#define BB   4
#define LL   2048
#define AD   1024
#define NH   16
#define HD   64
#define MM   (BB*LL)   // 8192

// ---------------------------------------------------------------------------
// Scratch (device globals)
// ---------------------------------------------------------------------------
__device__ __half g_acts [3 * MM * AD];    // fp16 activations q|k|v
__device__ __half g_wt   [4 * AD * AD];    // weights^T fp16 (q,k,v,o)
__device__ __half g_heads[3 * MM * AD];    // head planes Q(prescaled)|K|V
__device__ __half g_ao   [MM * AD];        // attention output fp16 [M,1024]

// ---------------------------------------------------------------------------
// Helpers (plain sm_103-legal: cp.async, ldmatrix, mma.sync)
// ---------------------------------------------------------------------------
__device__ __forceinline__ uint32_t smem_u32(const void* p) {
    uint32_t a;
    asm("{ .reg .u64 t; cvta.to.shared.u64 t, %1; cvt.u32.u64 %0, t; }" : "=r"(a) : "l"(p));
    return a;
}
#define CP_COMMIT()  asm volatile("cp.async.commit_group;" ::: "memory")
#define CP_WAIT(n)   asm volatile("cp.async.wait_group %0;" :: "n"(n) : "memory")

__device__ __forceinline__ uint32_t pack_h2(__half a, __half b) {
    return (uint32_t)__half_as_ushort(a) | ((uint32_t)__half_as_ushort(b) << 16);
}
__device__ __forceinline__ uint32_t h2_u(__half2 v) { return *reinterpret_cast<uint32_t*>(&v); }
__device__ __forceinline__ __half2  u_h2(uint32_t v) { return *reinterpret_cast<__half2*>(&v); }

__device__ __forceinline__ void ldm_x4(uint32_t& r0, uint32_t& r1, uint32_t& r2, uint32_t& r3,
                                       uint32_t addr) {
    asm volatile("ldmatrix.sync.aligned.m8n8.x4.shared.b16 {%0,%1,%2,%3}, [%4];"
                 : "=r"(r0), "=r"(r1), "=r"(r2), "=r"(r3) : "r"(addr));
}
__device__ __forceinline__ void ldm_x4_t(uint32_t& r0, uint32_t& r1, uint32_t& r2, uint32_t& r3,
                                         uint32_t addr) {
    asm volatile("ldmatrix.sync.aligned.m8n8.x4.trans.shared.b16 {%0,%1,%2,%3}, [%4];"
                 : "=r"(r0), "=r"(r1), "=r"(r2), "=r"(r3) : "r"(addr));
}
// fp32-accumulator mma
__device__ __forceinline__ void mma16816(float* d, const uint32_t* a, uint32_t b0, uint32_t b1) {
    asm volatile(
        "mma.sync.aligned.m16n8k16.row.col.f32.f16.f16.f32 "
        "{%0,%1,%2,%3}, {%4,%5,%6,%7}, {%8,%9}, {%0,%1,%2,%3};"
        : "+f"(d[0]), "+f"(d[1]), "+f"(d[2]), "+f"(d[3])
        : "r"(a[0]), "r"(a[1]), "r"(a[2]), "r"(a[3]), "r"(b0), "r"(b1));
}
// fp16-accumulator mma (d packed half2 x2; layout == A-fragment layout)
__device__ __forceinline__ void mma16816h(uint32_t* d, const uint32_t* a, uint32_t b0, uint32_t b1) {
    asm volatile(
        "mma.sync.aligned.m16n8k16.row.col.f16.f16.f16.f16 "
        "{%0,%1}, {%2,%3,%4,%5}, {%6,%7}, {%0,%1};"
        : "+r"(d[0]), "+r"(d[1])
        : "r"(a[0]), "r"(a[1]), "r"(a[2]), "r"(a[3]), "r"(b0), "r"(b1));
}

// ---------------------------------------------------------------------------
// conv_act fused: 3 inputs fp32 [M,1024] -> fp16, selected by blockIdx.y
// ---------------------------------------------------------------------------
__global__ void conv_act3(const float* __restrict__ X0, const float* __restrict__ X1,
                          const float* __restrict__ X2, __half* __restrict__ Y)
{
    const int z = blockIdx.y;
    const float* X = (z == 0) ? X0 : (z == 1) ? X1 : X2;
    int m = blockIdx.x;
    int c = threadIdx.x * 4;
    float4 v = *reinterpret_cast<const float4*>(X + (size_t)m * AD + c);
    uint2 o;
    o.x = pack_h2(__float2half_rn(v.x), __float2half_rn(v.y));
    o.y = pack_h2(__float2half_rn(v.z), __float2half_rn(v.w));
    *reinterpret_cast<uint2*>(Y + (size_t)z * MM * AD + (size_t)m * AD + c) = o;
}

// ---------------------------------------------------------------------------
// conv_wt fused: 4 weights W[K][N] fp32 -> Wt[N][K] fp16, selected by blockIdx.z
// ---------------------------------------------------------------------------
__global__ void conv_wt4(const float* __restrict__ W0, const float* __restrict__ W1,
                         const float* __restrict__ W2, const float* __restrict__ W3,
                         __half* __restrict__ WtBase)
{
    __shared__ float s[32][33];
    const int z = blockIdx.z;
    const float* W = (z == 0) ? W0 : (z == 1) ? W1 : (z == 2) ? W2 : W3;
    __half* Wt = WtBase + (size_t)z * AD * AD;
    int n0 = blockIdx.x * 32;
    int k0 = blockIdx.y * 32;
    int tx = threadIdx.x, ty = threadIdx.y;   // (32, 8)
#pragma unroll
    for (int i = 0; i < 4; ++i)
        s[ty + 8 * i][tx] = W[(size_t)(k0 + ty + 8 * i) * AD + n0 + tx];
    __syncthreads();
#pragma unroll
    for (int i = 0; i < 4; ++i) {
        int n = n0 + ty + 8 * i;
        int k = k0 + tx;
        Wt[(size_t)n * AD + k] = __float2half_rn(s[tx][ty + 8 * i]);
    }
}

// ---------------------------------------------------------------------------
// fp16 mma GEMM core (unchanged, proven).
// ---------------------------------------------------------------------------
#define GK_NC 16
#define SA0   0
#define SA1   16384
#define SB0   32768
#define SB1   49152
#define G_SMEM 65536

__device__ __forceinline__ void load_tile_cp(uint32_t sbase, uint32_t soff,
                                             const __half* __restrict__ g,
                                             int row0, int kc, int tid)
{
#pragma unroll
    for (int i = 0; i < 4; ++i) {
        int idx = i * 256 + tid;
        int r = idx >> 3, seg = idx & 7;
        const char* src = (const char*)g + ((size_t)(row0 + r) * AD + kc) * 2 + seg * 16;
        uint32_t dst = sbase + soff + r * 128 + ((seg * 16) ^ ((r & 7) * 16));
        asm volatile("cp.async.cg.shared.global [%0], [%1], 16;" :: "r"(dst), "l"(src));
    }
}

__device__ __forceinline__ void gemm_body(const __half* __restrict__ A,
                                          const __half* __restrict__ Bt,
                                          const float* __restrict__ bias,
                                          float* __restrict__ C,
                                          __half* __restrict__ outH,
                                          float oscale,
                                          char* smem)
{
    const uint32_t sbase = smem_u32(smem);
    const int tid  = threadIdx.x;
    const int warp = tid >> 5;
    const int lane = tid & 31;
    const int bn = blockIdx.x * 128;
    const int bm = blockIdx.y * 128;

    const int wm0 = (warp >> 2) * 64;
    const int wn0 = (warp & 3) * 32;

    float d[4][4][4];
#pragma unroll
    for (int im = 0; im < 4; ++im)
#pragma unroll
        for (int jt = 0; jt < 4; ++jt)
#pragma unroll
            for (int q = 0; q < 4; ++q) d[im][jt][q] = 0.f;

    uint32_t a_rb[4], a_sw[4];
#pragma unroll
    for (int im = 0; im < 4; ++im) {
        int row = wm0 + im * 16 + (lane & 15);
        a_rb[im] = row * 128;
        a_sw[im] = (row & 7) * 16;
    }
    const uint32_t a_kb = (lane >> 4) * 16;
    uint32_t b_rb[2], b_sw[2];
#pragma unroll
    for (int jn = 0; jn < 2; ++jn) {
        int row = wn0 + jn * 16 + (lane & 7) + ((lane >> 4) << 3);
        b_rb[jn] = row * 128;
        b_sw[jn] = (row & 7) * 16;
    }
    const uint32_t b_kb = ((lane >> 3) & 1) * 16;

    load_tile_cp(sbase, SA0, A,  bm, 0, tid);
    load_tile_cp(sbase, SB0, Bt, bn, 0, tid);
    CP_COMMIT();

    for (int i = 0; i < GK_NC; ++i) {
        const uint32_t aoff = (i & 1) ? SA1 : SA0;
        const uint32_t boff = (i & 1) ? SB1 : SB0;
        if (i + 1 < GK_NC) {
            load_tile_cp(sbase, (i & 1) ? SA0 : SA1, A,  bm, (i + 1) * 64, tid);
            load_tile_cp(sbase, (i & 1) ? SB0 : SB1, Bt, bn, (i + 1) * 64, tid);
            CP_COMMIT();
            CP_WAIT(1);
        } else {
            CP_WAIT(0);
        }
        __syncthreads();

#pragma unroll
        for (int ks = 0; ks < 4; ++ks) {
            const uint32_t kb = ks * 32;
            uint32_t af[4][4];
#pragma unroll
            for (int im = 0; im < 4; ++im)
                ldm_x4(af[im][0], af[im][1], af[im][2], af[im][3],
                       sbase + aoff + a_rb[im] + ((kb + a_kb) ^ a_sw[im]));
            uint32_t bf[4][2];
#pragma unroll
            for (int jn = 0; jn < 2; ++jn) {
                uint32_t r0, r1, r2, r3;
                ldm_x4(r0, r1, r2, r3,
                       sbase + boff + b_rb[jn] + ((kb + b_kb) ^ b_sw[jn]));
                bf[jn * 2][0] = r0; bf[jn * 2][1] = r1;
                bf[jn * 2 + 1][0] = r2; bf[jn * 2 + 1][1] = r3;
            }
#pragma unroll
            for (int im = 0; im < 4; ++im)
#pragma unroll
                for (int jt = 0; jt < 4; ++jt)
                    mma16816(d[im][jt], af[im], bf[jt][0], bf[jt][1]);
        }
        __syncthreads();
    }

    if (outH == nullptr) {
#pragma unroll
        for (int jt = 0; jt < 4; ++jt) {
            const int c0 = bn + wn0 + jt * 8 + 2 * (lane & 3);
            float2 bb = *reinterpret_cast<const float2*>(bias + c0);
#pragma unroll
            for (int im = 0; im < 4; ++im) {
                const int r0 = bm + wm0 + im * 16 + (lane >> 2);
                float2 o0 = make_float2(d[im][jt][0] + bb.x, d[im][jt][1] + bb.y);
                float2 o1 = make_float2(d[im][jt][2] + bb.x, d[im][jt][3] + bb.y);
                *reinterpret_cast<float2*>(C + (size_t)r0 * AD + c0)       = o0;
                *reinterpret_cast<float2*>(C + (size_t)(r0 + 8) * AD + c0) = o1;
            }
        }
    } else {
        // fp16 head-plane epilogue: [(b*NH+h)][L][64]
#pragma unroll
        for (int jt = 0; jt < 4; ++jt) {
            const int c0 = bn + wn0 + jt * 8 + 2 * (lane & 3);
            float2 bb = *reinterpret_cast<const float2*>(bias + c0);
            const int hh = c0 >> 6, dd = c0 & 63;
#pragma unroll
            for (int im = 0; im < 4; ++im) {
                const int r0 = bm + wm0 + im * 16 + (lane >> 2);
#pragma unroll
                for (int half = 0; half < 2; ++half) {
                    const int r = r0 + half * 8;
                    float v0 = (d[im][jt][half * 2 + 0] + bb.x) * oscale;
                    float v1 = (d[im][jt][half * 2 + 1] + bb.y) * oscale;
                    size_t addr = ((size_t)((r >> 11) * NH + hh) * LL + (r & 2047)) * HD + dd;
                    *reinterpret_cast<uint32_t*>(outH + addr) =
                        pack_h2(__float2half_rn(v0), __float2half_rn(v1));
                }
            }
        }
    }
}

// Fused QKV wrapper: blockIdx.z in {0,1,2} selects the projection.
struct QkvArgs {
    const __half* A;
    const __half* W;
    const float*  bias[3];
    __half*       outH;
};

// Q prescale folds softmax scale AND log2(e) so attention works in base-2.
#define Q_PRESCALE (0.125f * 1.4426950408889634f)

__global__ __launch_bounds__(256, 2)
void gemm_qkv(QkvArgs a)
{
    extern __shared__ char smem[];
    const int z = blockIdx.z;
    const float oscale = (z == 0) ? Q_PRESCALE : 1.0f;
    gemm_body(a.A + (size_t)z * MM * AD,
              a.W + (size_t)z * AD * AD,
              a.bias[z],
              nullptr,
              a.outH + (size_t)z * MM * AD,
              oscale, smem);
}

__global__ __launch_bounds__(256, 2)
void gemm_out(const __half* __restrict__ A, const __half* __restrict__ Bt,
              const float* __restrict__ bias, float* __restrict__ C)
{
    extern __shared__ char smem[];
    gemm_body(A, Bt, bias, C, nullptr, 1.0f, smem);
}

// ---------------------------------------------------------------------------
// fp16 mma flash attention — packed-half2 softmax build.
//  * QK uses fp16 accumulators: S lands pre-packed in A-fragment layout
//  * max via __hmax2 trees, exp via __hsub2 + h2exp2 (no cvt/pack at all)
//  * row-sums l computed BY THE TENSOR CORE via a constant "ones" B-fragment
// CTA = 64 q-rows; 128 threads / 4 warps; warp owns 16 rows; KV chunks 128.
// ---------------------------------------------------------------------------
#define AT_Q   0
#define AT_BUF 8192                     // + buf*32768 ; Kh at +0, Vh at +16384
#define AT_SMEM (8192 + 2*32768)        // 73728

__device__ __forceinline__ void at_load_plane(uint32_t sb, uint32_t soff,
                                              const __half* __restrict__ g,
                                              size_t pbase, int row0, int nrows, int tid)
{
    const int iters = nrows / 16;
#pragma unroll
    for (int i = 0; i < 8; ++i) {
        if (i >= iters) break;
        int idx = i * 128 + tid;
        int r = idx >> 3, seg = idx & 7;
        const char* src = (const char*)(g + pbase + (size_t)(row0 + r) * HD) + seg * 16;
        uint32_t dst = sb + soff + r * 128 + ((seg * 16) ^ ((r & 7) * 16));
        asm volatile("cp.async.cg.shared.global [%0], [%1], 16;" :: "r"(dst), "l"(src));
    }
}

__global__ __launch_bounds__(128, 3)
void attn_mma(const __half* __restrict__ Qh,
              const __half* __restrict__ Kh,
              const __half* __restrict__ Vh,
              __half* __restrict__ Oatt)
{
    extern __shared__ char smem[];
    const uint32_t sb = smem_u32(smem);
    const int tid  = threadIdx.x;
    const int warp = tid >> 5;
    const int lane = tid & 31;
    const int gidr = lane >> 2;
    const int tg   = lane & 3;

    const int qt = blockIdx.x, h = blockIdx.y, b = blockIdx.z;
    const size_t pbase = (size_t)(b * NH + h) * LL * HD;
    const int q0 = qt * 64;

    at_load_plane(sb, AT_Q, Qh, pbase, q0, 64, tid);
    CP_COMMIT();
    at_load_plane(sb, AT_BUF,         Kh, pbase, 0, 128, tid);
    at_load_plane(sb, AT_BUF + 16384, Vh, pbase, 0, 128, tid);
    CP_COMMIT();
    at_load_plane(sb, AT_BUF + 32768, Kh, pbase, 128, 128, tid);
    at_load_plane(sb, AT_BUF + 49152, Vh, pbase, 128, 128, tid);
    CP_COMMIT();

    const uint32_t a_row = 16 * warp + (lane & 15);
    const uint32_t a_off = a_row * 128;
    const uint32_t a_sw  = (a_row & 7) * 16;
    const uint32_t a_kb  = (lane >> 4) * 16;
    const uint32_t b_rowb = (lane & 7) + ((lane >> 4) << 3);
    const uint32_t b_kb   = ((lane >> 3) & 1) * 16;
    const uint32_t v_rowb = (lane & 15);
    const uint32_t v_cb   = (lane >> 4) * 16;

    // constant "ones" B-fragment: b[k][n]=1 for tile-col n==0 (global col 64)
    const uint32_t ones = ((lane >> 2) == 0) ? 0x3C003C00u : 0u;

    float m0 = -1e30f, m1 = -1e30f;
    float O[8][4];
    float Ol[4];   // ones-column accumulator: Ol[0]=l(row gidr), Ol[2]=l(row gidr+8) at tg==0
#pragma unroll
    for (int j = 0; j < 8; ++j)
#pragma unroll
        for (int q = 0; q < 4; ++q) O[j][q] = 0.f;
#pragma unroll
    for (int q = 0; q < 4; ++q) Ol[q] = 0.f;

    for (int ci = 0; ci < 16; ++ci) {
        if (ci < 15) { CP_WAIT(1); } else { CP_WAIT(0); }
        __syncthreads();

        const uint32_t kh_ = sb + AT_BUF + (ci & 1) * 32768;
        const uint32_t vh_ = kh_ + 16384;

        // ---- S = Q K^T, fp16 accumulators (pre-packed, A-fragment layout) ----
        uint32_t sh[16][2];
#pragma unroll
        for (int j = 0; j < 16; ++j) { sh[j][0] = 0u; sh[j][1] = 0u; }

#pragma unroll
        for (int ks = 0; ks < 4; ++ks) {
            const uint32_t kb = ks * 32;
            uint32_t af[4];
            ldm_x4(af[0], af[1], af[2], af[3], sb + AT_Q + a_off + ((kb + a_kb) ^ a_sw));
#pragma unroll
            for (int jj = 0; jj < 8; ++jj) {
                uint32_t row = 16 * jj + b_rowb;
                uint32_t r0, r1, r2, r3;
                ldm_x4(r0, r1, r2, r3, kh_ + row * 128 + ((kb + b_kb) ^ ((row & 7) * 16)));
                mma16816h(sh[2 * jj],     af, r0, r1);
                mma16816h(sh[2 * jj + 1], af, r2, r3);
            }
        }

        // ---- online softmax in packed fp16 (base-2 domain) ----
        __half2 cx0 = u_h2(sh[0][0]), cx1 = u_h2(sh[0][1]);
#pragma unroll
        for (int j = 1; j < 16; ++j) {
            cx0 = __hmax2(cx0, u_h2(sh[j][0]));
            cx1 = __hmax2(cx1, u_h2(sh[j][1]));
        }
        float cm0 = fmaxf(__low2float(cx0), __high2float(cx0));
        float cm1 = fmaxf(__low2float(cx1), __high2float(cx1));
        cm0 = fmaxf(cm0, __shfl_xor_sync(0xffffffffu, cm0, 1));
        cm0 = fmaxf(cm0, __shfl_xor_sync(0xffffffffu, cm0, 2));
        cm1 = fmaxf(cm1, __shfl_xor_sync(0xffffffffu, cm1, 1));
        cm1 = fmaxf(cm1, __shfl_xor_sync(0xffffffffu, cm1, 2));
        const float mn0 = fmaxf(m0, cm0);
        const float mn1 = fmaxf(m1, cm1);
        const float corr0 = exp2f(m0 - mn0);
        const float corr1 = exp2f(m1 - mn1);
        m0 = mn0; m1 = mn1;
#pragma unroll
        for (int j = 0; j < 8; ++j) {
            O[j][0] *= corr0; O[j][1] *= corr0;
            O[j][2] *= corr1; O[j][3] *= corr1;
        }
        Ol[0] *= corr0; Ol[1] *= corr0;
        Ol[2] *= corr1; Ol[3] *= corr1;

        const __half2 mh0 = __floats2half2_rn(mn0, mn0);
        const __half2 mh1 = __floats2half2_rn(mn1, mn1);
#pragma unroll
        for (int j = 0; j < 16; ++j) {
            sh[j][0] = h2_u(h2exp2(__hsub2(u_h2(sh[j][0]), mh0)));
            sh[j][1] = h2_u(h2exp2(__hsub2(u_h2(sh[j][1]), mh1)));
        }

        // ---- PV + l: P fragments are pure register renames ----
#pragma unroll
        for (int kk = 0; kk < 8; ++kk) {
            uint32_t ah[4] = { sh[2*kk][0], sh[2*kk][1], sh[2*kk+1][0], sh[2*kk+1][1] };

            mma16816(Ol, ah, ones, ones);   // row-sums into column "64"

            const uint32_t vrow = 16 * kk + v_rowb;
            const uint32_t vsw  = (vrow & 7) * 16;
            const uint32_t vaddr = vh_ + vrow * 128;
#pragma unroll
            for (int nb = 0; nb < 4; ++nb) {
                uint32_t r0, r1, r2, r3;
                ldm_x4_t(r0, r1, r2, r3, vaddr + (((uint32_t)(nb * 32) + v_cb) ^ vsw));
                mma16816(O[2 * nb],     ah, r0, r1);
                mma16816(O[2 * nb + 1], ah, r2, r3);
            }
        }

        __syncthreads();   // all warps done reading buf (ci&1)
        if (ci + 2 < 16) {
            uint32_t bb = AT_BUF + (ci & 1) * 32768;
            int row0 = (ci + 2) * 128;
            at_load_plane(sb, bb,         Kh, pbase, row0, 128, tid);
            at_load_plane(sb, bb + 16384, Vh, pbase, row0, 128, tid);
            CP_COMMIT();
        }
    }

    // ---- epilogue: fetch l from quad-leader (tg==0 holds col 64), store ----
    const float l0 = __shfl_sync(0xffffffffu, Ol[0], lane & 28);
    const float l1 = __shfl_sync(0xffffffffu, Ol[2], lane & 28);
    const float inv0 = 1.f / l0;
    const float inv1 = 1.f / l1;
    const int colb = h * HD + 2 * tg;
#pragma unroll
    for (int jf = 0; jf < 8; ++jf) {
#pragma unroll
        for (int half = 0; half < 2; ++half) {
            const int r = 16 * warp + gidr + half * 8;
            const float inv = half ? inv1 : inv0;
            float v0 = O[jf][half * 2 + 0] * inv;
            float v1 = O[jf][half * 2 + 1] * inv;
            size_t addr = (size_t)(b * LL + q0 + r) * AD + colb + 8 * jf;
            *reinterpret_cast<uint32_t*>(Oatt + addr) =
                pack_h2(__float2half_rn(v0), __float2half_rn(v1));
        }
    }
}

// ---------------------------------------------------------------------------
// Launch: 5 kernels total
// ---------------------------------------------------------------------------
extern "C" void kernel_launch(void* const* d_in, const int* in_sizes, int n_in,
                              void* d_out, int out_size)
{
    const float* query = (const float*)d_in[0];
    const float* key   = (const float*)d_in[1];
    const float* value = (const float*)d_in[2];
    const float* Wq = (const float*)d_in[3];
    const float* bq = (const float*)d_in[4];
    const float* Wk = (const float*)d_in[5];
    const float* bk = (const float*)d_in[6];
    const float* Wv = (const float*)d_in[7];
    const float* bv = (const float*)d_in[8];
    const float* Wo = (const float*)d_in[9];
    const float* bo = (const float*)d_in[10];
    float* out = (float*)d_out;

    __half *pacts, *pwt, *pheads, *pao;
    cudaGetSymbolAddress((void**)&pacts,  g_acts);
    cudaGetSymbolAddress((void**)&pwt,    g_wt);
    cudaGetSymbolAddress((void**)&pheads, g_heads);
    cudaGetSymbolAddress((void**)&pao,    g_ao);

    cudaFuncSetAttribute(gemm_qkv, cudaFuncAttributeMaxDynamicSharedMemorySize, G_SMEM);
    cudaFuncSetAttribute(gemm_out, cudaFuncAttributeMaxDynamicSharedMemorySize, G_SMEM);
    cudaFuncSetAttribute(attn_mma, cudaFuncAttributeMaxDynamicSharedMemorySize, AT_SMEM);

    // 1) all weight transposes
    dim3 wgrid(32, 32, 4), wblk(32, 8);
    conv_wt4<<<wgrid, wblk>>>(Wq, Wk, Wv, Wo, pwt);

    // 2) all activation conversions
    dim3 cgrid(MM, 3);
    conv_act3<<<cgrid, 256>>>(query, key, value, pacts);

    // 3) fused QKV projection GEMM
    QkvArgs qa;
    qa.A = pacts; qa.W = pwt; qa.outH = pheads;
    qa.bias[0] = bq; qa.bias[1] = bk; qa.bias[2] = bv;
    dim3 ggrid(AD / 128, MM / 128, 3);   // (8, 64, 3)
    gemm_qkv<<<ggrid, 256, G_SMEM>>>(qa);

    // 4) attention
    dim3 agrid(LL / 64, NH, BB);         // (32, 16, 4)
    attn_mma<<<agrid, 128, AT_SMEM>>>(pheads,
                                      pheads + (size_t)MM * AD,
                                      pheads + 2 * (size_t)MM * AD,
                                      pao);

    // 5) output projection
    dim3 ogrid(AD / 128, MM / 128);      // (8, 64)
    gemm_out<<<ogrid, 256, G_SMEM>>>(pao, pwt + 3 * (size_t)AD * AD, bo, out);
}